// round 12
// baseline (speedup 1.0000x reference)
#include <cuda_runtime.h>
#include <cuda_bf16.h>

// ---------------------------------------------------------------------------
// GraphConvNet: B=8, V=2048, D=3, CL1(K=6,F=64), CL2(K=5,F=128), FC 512, 256
// All fp32. Heavy lifting = batched L@X GEMMs, done with packed fma.rn.f32x2.
// ---------------------------------------------------------------------------

#define BATCH 8
#define NV    2048
#define NROWS (BATCH * NV)      // 16384

// scratch (device globals; no allocation allowed)
__device__ float g_xk1[(size_t)NROWS * 18];          // conv1 Chebyshev basis, feature = fin*6 + k
__device__ float g_z[(size_t)5 * NROWS * 64];        // conv2 Chebyshev basis slabs z0..z4
__device__ float g_xk2[(size_t)NROWS * 320];         // packed conv2 basis, feature = fin*5 + k
__device__ float g_y2[(size_t)NROWS * 128];
__device__ float g_h1[(size_t)NROWS * 512];

#define ZSLAB ((size_t)NROWS * 64)

// ------------------------- f32x2 packed-FMA helpers ------------------------
__device__ __forceinline__ unsigned long long pk2(float x, float y) {
    unsigned long long r;
    asm("mov.b64 %0, {%1, %2};" : "=l"(r) : "f"(x), "f"(y));
    return r;
}
__device__ __forceinline__ unsigned long long dup2(float x) {
    unsigned long long r;
    asm("mov.b64 %0, {%1, %1};" : "=l"(r) : "f"(x));
    return r;
}
__device__ __forceinline__ void fma2(unsigned long long& c,
                                     unsigned long long a, unsigned long long b) {
    asm("fma.rn.f32x2 %0, %1, %2, %0;" : "+l"(c) : "l"(a), "l"(b));
}
__device__ __forceinline__ float2 unpk2(unsigned long long v) {
    float2 f;
    asm("mov.b64 {%0, %1}, %2;" : "=f"(f.x), "=f"(f.y) : "l"(v));
    return f;
}

// ------------------------- transpose x [B,D,V] -> xk1 k=0 column -----------
__global__ void __launch_bounds__(256) k_xpose(const float* __restrict__ x,
                                               float* __restrict__ xk1) {
    int idx = blockIdx.x * 256 + threadIdx.x;           // over 8*3*2048
    if (idx >= BATCH * 3 * NV) return;
    int v = idx & (NV - 1);
    int d = (idx >> 11) % 3;
    int b = idx / (3 * NV);
    xk1[(size_t)(b * NV + v) * 18 + d * 6] = x[idx];
}

// ------------------------- conv1 Chebyshev step (Fin=3) --------------------
// xk1 col k  <-  alpha * L @ (col k-1)  +  beta * (col k-2)
__global__ void __launch_bounds__(256) k_cheby_small(
    const float* __restrict__ L, float* __restrict__ xk1,
    int kIdx, float alpha, float beta) {
    __shared__ float sx[3][NV];
    const int tid = threadIdx.x;
    const int b = blockIdx.y;
    const size_t bV = (size_t)b * NV;

    for (int c = tid; c < NV; c += 256) {
        const float* xr = xk1 + (bV + c) * 18 + (kIdx - 1);
        sx[0][c] = xr[0];
        sx[1][c] = xr[6];
        sx[2][c] = xr[12];
    }
    __syncthreads();

    const int warp = tid >> 5, lane = tid & 31;
    for (int rr = 0; rr < 8; rr++) {
        const int row = blockIdx.x * 64 + warp * 8 + rr;
        const float* Lr = L + (bV + row) * NV;
        float a0 = 0.f, a1 = 0.f, a2 = 0.f;
        #pragma unroll 8
        for (int c = lane; c < NV; c += 32) {
            float lv = Lr[c];
            a0 += lv * sx[0][c];
            a1 += lv * sx[1][c];
            a2 += lv * sx[2][c];
        }
        #pragma unroll
        for (int off = 16; off > 0; off >>= 1) {
            a0 += __shfl_down_sync(0xffffffffu, a0, off);
            a1 += __shfl_down_sync(0xffffffffu, a1, off);
            a2 += __shfl_down_sync(0xffffffffu, a2, off);
        }
        if (lane == 0) {
            float* orow = xk1 + (bV + row) * 18;
            float p0 = 0.f, p1 = 0.f, p2 = 0.f;
            if (beta != 0.f) {
                p0 = orow[kIdx - 2];
                p1 = orow[6 + kIdx - 2];
                p2 = orow[12 + kIdx - 2];
            }
            orow[kIdx]      = alpha * a0 + beta * p0;
            orow[6 + kIdx]  = alpha * a1 + beta * p1;
            orow[12 + kIdx] = alpha * a2 + beta * p2;
        }
    }
}

// ------------------------- conv1 linear: y1 = relu(xk1 @ W1^T + b1) --------
__global__ void __launch_bounds__(256) k_conv1_lin(
    const float* __restrict__ xk1, const float* __restrict__ W,
    const float* __restrict__ bias, float* __restrict__ z0) {
    __shared__ float sW[64 * 18];
    __shared__ float sb[64];
    __shared__ float sx[4 * 18];
    const int tid = threadIdx.x;
    for (int i = tid; i < 64 * 18; i += 256) sW[i] = W[i];
    if (tid < 64) sb[tid] = bias[tid];
    const int row0 = blockIdx.x * 4;
    if (tid < 72) sx[tid] = xk1[(size_t)row0 * 18 + tid];
    __syncthreads();
    const int r = tid >> 6;
    const int fo = tid & 63;
    float acc = sb[fo];
    #pragma unroll
    for (int j = 0; j < 18; j++) acc += sx[r * 18 + j] * sW[fo * 18 + j];
    z0[(size_t)(row0 + r) * 64 + fo] = acc > 0.f ? acc : 0.f;
}

// ------------------------- pack conv2 basis into [row, fin*5+k] ------------
__global__ void __launch_bounds__(256) k_pack2(const float* __restrict__ z,
                                               float* __restrict__ xk2) {
    size_t idx = (size_t)blockIdx.x * 256 + threadIdx.x;   // over 16384*64
    size_t row = idx >> 6;
    int fin = (int)(idx & 63);
    float* o = xk2 + row * 320 + fin * 5;
    #pragma unroll
    for (int k = 0; k < 5; k++) o[k] = z[(size_t)k * ZSLAB + idx];
}

// ------------------------- main GEMM tile kernel ---------------------------
// C[M,N] tiles of 128x64. WTRANS: B is W[N,K] row-major (ldb=K), used as B^T.
// RELUB: C = relu(A@B + bias[n]).  else: C = alpha*A@B + beta*P (P same layout as C).
#define T_BM 128
#define T_BN 64
#define T_BK 16
#define ASTR 132
#define BSTR 68

template <bool WTRANS, bool RELUB>
__global__ void __launch_bounds__(256) k_gemm(
    const float* __restrict__ A, int lda, size_t strideA,
    const float* __restrict__ B, int ldb, size_t strideB,
    float* __restrict__ C, int ldc, size_t strideC,
    const float* __restrict__ P, size_t strideP,
    float alpha, float beta, int K) {
    __shared__ float As[T_BK * ASTR];
    __shared__ float Bs[T_BK * BSTR];
    const int tid = threadIdx.x;
    const int bz = blockIdx.z;
    A += (size_t)bz * strideA;
    B += (size_t)bz * strideB;
    C += (size_t)bz * strideC;
    P += (size_t)bz * strideP;
    const int m0 = blockIdx.y * T_BM;
    const int n0 = blockIdx.x * T_BN;

    const int tx = tid & 15;   // col group: 4 cols each
    const int ty = tid >> 4;   // row group: 8 rows each

    unsigned long long acc[4][4];
    #pragma unroll
    for (int p = 0; p < 4; p++)
        #pragma unroll
        for (int j = 0; j < 4; j++) acc[p][j] = 0ull;

    const int arow = tid >> 2;
    const int acol = (tid & 3) * 4;
    const int brow = tid >> 4;
    const int bcol = (tid & 15) * 4;

    for (int kt = 0; kt < K; kt += T_BK) {
        // ---- A tile: As[k][m] ----
        #pragma unroll
        for (int r = 0; r < 2; r++) {
            const int gm = m0 + arow + r * 64;
            const float4 v = *reinterpret_cast<const float4*>(
                A + (size_t)gm * lda + kt + acol);
            As[(acol + 0) * ASTR + arow + r * 64] = v.x;
            As[(acol + 1) * ASTR + arow + r * 64] = v.y;
            As[(acol + 2) * ASTR + arow + r * 64] = v.z;
            As[(acol + 3) * ASTR + arow + r * 64] = v.w;
        }
        // ---- B tile: Bs[k][n] ----
        if (WTRANS) {
            const float4 v = *reinterpret_cast<const float4*>(
                B + (size_t)(n0 + arow) * ldb + kt + acol);
            Bs[(acol + 0) * BSTR + arow] = v.x;
            Bs[(acol + 1) * BSTR + arow] = v.y;
            Bs[(acol + 2) * BSTR + arow] = v.z;
            Bs[(acol + 3) * BSTR + arow] = v.w;
        } else {
            const float4 v = *reinterpret_cast<const float4*>(
                B + (size_t)(kt + brow) * ldb + n0 + bcol);
            *reinterpret_cast<float4*>(&Bs[brow * BSTR + bcol]) = v;
        }
        __syncthreads();
        #pragma unroll
        for (int k = 0; k < T_BK; k++) {
            const float4 a0 = *reinterpret_cast<const float4*>(&As[k * ASTR + ty * 8]);
            const float4 a1 = *reinterpret_cast<const float4*>(&As[k * ASTR + ty * 8 + 4]);
            unsigned long long av[4];
            av[0] = pk2(a0.x, a0.y);
            av[1] = pk2(a0.z, a0.w);
            av[2] = pk2(a1.x, a1.y);
            av[3] = pk2(a1.z, a1.w);
            const float4 b4 = *reinterpret_cast<const float4*>(&Bs[k * BSTR + tx * 4]);
            unsigned long long bv[4];
            bv[0] = dup2(b4.x);
            bv[1] = dup2(b4.y);
            bv[2] = dup2(b4.z);
            bv[3] = dup2(b4.w);
            #pragma unroll
            for (int p = 0; p < 4; p++)
                #pragma unroll
                for (int j = 0; j < 4; j++) fma2(acc[p][j], av[p], bv[j]);
        }
        __syncthreads();
    }

    // ---- epilogue ----
    const int gn = n0 + tx * 4;
    #pragma unroll
    for (int p = 0; p < 4; p++) {
        float rows[2][4];
        #pragma unroll
        for (int j = 0; j < 4; j++) {
            float2 f = unpk2(acc[p][j]);
            rows[0][j] = f.x;
            rows[1][j] = f.y;
        }
        #pragma unroll
        for (int h = 0; h < 2; h++) {
            const int gm = m0 + ty * 8 + 2 * p + h;
            float* crow = C + (size_t)gm * ldc + gn;
            if (RELUB) {
                #pragma unroll
                for (int j = 0; j < 4; j++) {
                    float v = rows[h][j] + P[gn + j];
                    crow[j] = v > 0.f ? v : 0.f;
                }
            } else if (beta != 0.f) {
                const float* prow = P + (size_t)gm * ldc + gn;
                #pragma unroll
                for (int j = 0; j < 4; j++)
                    crow[j] = alpha * rows[h][j] + beta * prow[j];
            } else {
                #pragma unroll
                for (int j = 0; j < 4; j++) crow[j] = alpha * rows[h][j];
            }
        }
    }
}

// ---------------------------------------------------------------------------
extern "C" void kernel_launch(void* const* d_in, const int* in_sizes, int n_in,
                              void* d_out, int out_size) {
    (void)in_sizes; (void)n_in; (void)out_size;
    const float* x   = (const float*)d_in[0];
    const float* L   = (const float*)d_in[1];
    const float* w1  = (const float*)d_in[2];
    const float* b1  = (const float*)d_in[3];
    const float* w2  = (const float*)d_in[4];
    const float* b2  = (const float*)d_in[5];
    const float* fw1 = (const float*)d_in[6];
    const float* fb1 = (const float*)d_in[7];
    const float* fw2 = (const float*)d_in[8];
    const float* fb2 = (const float*)d_in[9];
    float* out = (float*)d_out;

    float *xk1, *z, *xk2, *y2, *h1;
    cudaGetSymbolAddress((void**)&xk1, g_xk1);
    cudaGetSymbolAddress((void**)&z,   g_z);
    cudaGetSymbolAddress((void**)&xk2, g_xk2);
    cudaGetSymbolAddress((void**)&y2,  g_y2);
    cudaGetSymbolAddress((void**)&h1,  g_h1);

    // 1) x0 = x^T into xk1 (k=0)
    k_xpose<<<192, 256>>>(x, xk1);

    // 2) conv1 Chebyshev recurrence (K=6 -> steps k=1..5), Fin=3
    k_cheby_small<<<dim3(32, 8), 256>>>(L, xk1, 1, 1.f, 0.f);
    for (int k = 2; k <= 5; k++)
        k_cheby_small<<<dim3(32, 8), 256>>>(L, xk1, k, 2.f, -1.f);

    // 3) y1 = relu(xk1 @ W1^T + b1) -> z slab 0
    k_conv1_lin<<<NROWS / 4, 256>>>(xk1, w1, b1, z);

    // 4) conv2 Chebyshev recurrence (K=5 -> steps k=1..4), Fin=64: batched L@z GEMMs
    for (int k = 1; k <= 4; k++) {
        const float* zprev = z + (size_t)(k - 1) * ZSLAB;
        const float* zpp   = (k >= 2) ? z + (size_t)(k - 2) * ZSLAB : z;
        float* zk = z + (size_t)k * ZSLAB;
        float alpha = (k == 1) ? 1.f : 2.f;
        float beta  = (k == 1) ? 0.f : -1.f;
        k_gemm<false, false><<<dim3(1, NV / T_BM, BATCH), 256>>>(
            L, NV, (size_t)NV * NV,
            zprev, 64, (size_t)NV * 64,
            zk, 64, (size_t)NV * 64,
            zpp, (size_t)NV * 64,
            alpha, beta, NV);
    }

    // 5) pack z slabs -> xk2 [rows, fin*5+k]
    k_pack2<<<(NROWS * 64) / 256, 256>>>(z, xk2);

    // 6) y2 = relu(xk2 @ W2^T + b2)   [16384,320] x [320->128]
    k_gemm<true, true><<<dim3(128 / T_BN, NROWS / T_BM, 1), 256>>>(
        xk2, 320, 0, w2, 320, 0, y2, 128, 0, b2, 0, 1.f, 0.f, 320);

    // 7) h1 = relu(y2 @ fc1_w^T + fb1)   [16384,128] -> 512
    k_gemm<true, true><<<dim3(512 / T_BN, NROWS / T_BM, 1), 256>>>(
        y2, 128, 0, fw1, 128, 0, h1, 512, 0, fb1, 0, 1.f, 0.f, 128);

    // 8) out = relu(h1 @ fc2_w^T + fb2)  [16384,512] -> 256
    k_gemm<true, true><<<dim3(256 / T_BN, NROWS / T_BM, 1), 256>>>(
        h1, 512, 0, fw2, 512, 0, out, 256, 0, fb2, 0, 1.f, 0.f, 512);
}